// round 1
// baseline (speedup 1.0000x reference)
#include <cuda_runtime.h>
#include <cstdint>

#define BSZ    256
#define FEAT   128
#define KP1    4097          // K + 1
#define NDATA  500000
#define SDIM   1024
#define TDIM   2048
#define MEMELEMS (NDATA * FEAT)   // 64,000,000
#define TOTAL  (BSZ * KP1)        // 1,048,832

__device__ float g_es[BSZ * FEAT];
__device__ float g_et[BSZ * FEAT];
__device__ float g_out_s[TOTAL];
__device__ float g_out_t[TOTAL];
__device__ float g_sums[3];   // [0]=sum out_t, [1]=sum out_s, [2]=loss accumulator

// ---------------------------------------------------------------- init
__global__ void init_kernel() {
    g_sums[0] = 0.f; g_sums[1] = 0.f; g_sums[2] = 0.f;
}

// ---------------------------------------------------------------- embeddings
// grid: 128 blocks (64 for es, 64 for et), 128 threads. 4 output rows/block.
__global__ void embed_kernel(const float* __restrict__ f_s, const float* __restrict__ f_t,
                             const float* __restrict__ W_s, const float* __restrict__ b_s,
                             const float* __restrict__ W_t, const float* __restrict__ b_t) {
    __shared__ float fsh[4 * 2048];
    __shared__ float sh[4];
    const bool is_t = blockIdx.x >= 64;
    const int  rb   = (is_t ? blockIdx.x - 64 : blockIdx.x) * 4;
    const float* f    = is_t ? f_t : f_s;
    const float* W    = is_t ? W_t : W_s;
    const float* bias = is_t ? b_t : b_s;
    float*       out  = is_t ? g_et : g_es;
    const int    Kd   = is_t ? TDIM : SDIM;
    const int t = threadIdx.x;

    #pragma unroll
    for (int r = 0; r < 4; ++r)
        for (int k = t; k < Kd; k += 128)
            fsh[r * 2048 + k] = f[(rb + r) * Kd + k];
    __syncthreads();

    float a0 = 0.f, a1 = 0.f, a2 = 0.f, a3 = 0.f;
    for (int k = 0; k < Kd; ++k) {
        float w = W[k * FEAT + t];
        a0 += fsh[k] * w;
        a1 += fsh[2048 + k] * w;
        a2 += fsh[4096 + k] * w;
        a3 += fsh[6144 + k] * w;
    }
    const float bb = bias[t];
    float acc[4] = {a0 + bb, a1 + bb, a2 + bb, a3 + bb};

    const int lane = t & 31, w_ = t >> 5;
    #pragma unroll
    for (int r = 0; r < 4; ++r) {
        float v = acc[r] * acc[r];
        #pragma unroll
        for (int o = 16; o; o >>= 1) v += __shfl_xor_sync(0xffffffffu, v, o);
        if (lane == 0) sh[w_] = v;
        __syncthreads();
        float tot = sh[0] + sh[1] + sh[2] + sh[3];
        __syncthreads();
        out[(rb + r) * FEAT + t] = acc[r] / sqrtf(tot);
    }
}

// ---------------------------------------------------------------- NCE gather + dot + exp
// One warp per (b,k) task, contiguous-chunk assignment so es/et stay in registers.
__global__ void nce_kernel(const int* __restrict__ cidx,
                           const float* __restrict__ m1, const float* __restrict__ m2) {
    const int lane = threadIdx.x & 31;
    const int wInB = threadIdx.x >> 5;
    const int nWarps = gridDim.x * (blockDim.x >> 5);
    const int wid = blockIdx.x * (blockDim.x >> 5) + wInB;
    const int chunk = (TOTAL + nWarps - 1) / nWarps;
    const int t0 = wid * chunk;
    const int t1 = min(t0 + chunk, TOTAL);

    float sumT = 0.f, sumS = 0.f;

    if (t0 < t1) {
        int b = t0 / KP1;
        int k = t0 - b * KP1;
        bool need = true;
        float4 es4, et4;
        for (int t = t0; t < t1; ++t) {
            if (need) {
                es4 = ((const float4*)(g_es + b * FEAT))[lane];
                et4 = ((const float4*)(g_et + b * FEAT))[lane];
                need = false;
            }
            int row = __ldg(cidx + t);
            const float4 a = __ldg((const float4*)(m1 + (size_t)row * FEAT) + lane);
            const float4 c = __ldg((const float4*)(m2 + (size_t)row * FEAT) + lane);
            float dt = a.x * et4.x + a.y * et4.y + a.z * et4.z + a.w * et4.w;
            float ds = c.x * es4.x + c.y * es4.y + c.z * es4.z + c.w * es4.w;
            #pragma unroll
            for (int o = 16; o; o >>= 1) {
                dt += __shfl_xor_sync(0xffffffffu, dt, o);
                ds += __shfl_xor_sync(0xffffffffu, ds, o);
            }
            if (lane == 0) {
                float ot = expf(dt * (1.0f / 0.07f));
                float os = expf(ds * (1.0f / 0.07f));
                g_out_t[t] = ot;
                g_out_s[t] = os;
                sumT += ot;
                sumS += os;
            }
            if (++k == KP1) { k = 0; ++b; need = true; }
        }
    }

    __shared__ float shT[8], shS[8];
    if (lane == 0) { shT[wInB] = sumT; shS[wInB] = sumS; }
    __syncthreads();
    if (threadIdx.x == 0) {
        float aT = 0.f, aS = 0.f;
        const int nw = blockDim.x >> 5;
        for (int i = 0; i < nw; ++i) { aT += shT[i]; aS += shS[i]; }
        atomicAdd(&g_sums[0], aT);
        atomicAdd(&g_sums[1], aS);
    }
}

// ---------------------------------------------------------------- loss
// grid: (ceil(KP1/256), BSZ), 256 threads
__global__ void loss_kernel() {
    const int k = blockIdx.x * blockDim.x + threadIdx.x;
    const int b = blockIdx.y;
    float acc = 0.f;
    if (k < KP1) {
        const float Zt = g_sums[0] * ((float)NDATA / (float)TOTAL);
        const float Zs = g_sums[1] * ((float)NDATA / (float)TOTAL);
        const float mPn = 4096.0f / (float)NDATA;
        const float EPSf = 1e-7f;
        const int i = b * KP1 + k;
        float xs = g_out_s[i] / Zs;
        float xt = g_out_t[i] / Zt;
        if (k == 0)
            acc = logf(xs / (xs + mPn + EPSf)) + logf(xt / (xt + mPn + EPSf));
        else
            acc = logf(mPn / (xs + mPn + EPSf)) + logf(mPn / (xt + mPn + EPSf));
    }
    #pragma unroll
    for (int o = 16; o; o >>= 1) acc += __shfl_xor_sync(0xffffffffu, acc, o);
    __shared__ float sh[8];
    const int lane = threadIdx.x & 31, w_ = threadIdx.x >> 5;
    if (lane == 0) sh[w_] = acc;
    __syncthreads();
    if (threadIdx.x == 0) {
        float tot = 0.f;
        for (int i = 0; i < 8; ++i) tot += sh[i];
        atomicAdd(&g_sums[2], tot);
    }
}

__global__ void finalize_kernel(float* __restrict__ out) {
    out[0] = -g_sums[2] / (float)BSZ;
}

// ---------------------------------------------------------------- memory copy-out
// float4 loads (src 16B-aligned), scalar stores (dst only 4B-aligned: d_out+1)
__global__ void copy_kernel(const float4* __restrict__ m1, const float4* __restrict__ m2,
                            float* __restrict__ o1, float* __restrict__ o2) {
    const int i = blockIdx.x * blockDim.x + threadIdx.x;
    if (i < MEMELEMS / 4) {
        float4 a = __ldg(m1 + i);
        float4 b = __ldg(m2 + i);
        const int j = i * 4;
        o1[j] = a.x; o1[j + 1] = a.y; o1[j + 2] = a.z; o1[j + 3] = a.w;
        o2[j] = b.x; o2[j + 1] = b.y; o2[j + 2] = b.z; o2[j + 3] = b.w;
    }
}

// ---------------------------------------------------------------- scatter update
// 256 blocks (one per batch row), 128 threads
__global__ void update_kernel(const int* __restrict__ idx,
                              const float* __restrict__ m1, const float* __restrict__ m2,
                              float* __restrict__ o1, float* __restrict__ o2) {
    const int b = blockIdx.x;
    const int t = threadIdx.x;
    const int row = __ldg(idx + b);
    const size_t off = (size_t)row * FEAT + t;
    float v1 = __ldg(m1 + off) * 0.5f + g_es[b * FEAT + t] * 0.5f;
    float v2 = __ldg(m2 + off) * 0.5f + g_et[b * FEAT + t] * 0.5f;
    float s1 = v1 * v1, s2 = v2 * v2;
    #pragma unroll
    for (int o = 16; o; o >>= 1) {
        s1 += __shfl_xor_sync(0xffffffffu, s1, o);
        s2 += __shfl_xor_sync(0xffffffffu, s2, o);
    }
    __shared__ float sh1[4], sh2[4];
    const int lane = t & 31, w_ = t >> 5;
    if (lane == 0) { sh1[w_] = s1; sh2[w_] = s2; }
    __syncthreads();
    float t1 = sh1[0] + sh1[1] + sh1[2] + sh1[3];
    float t2 = sh2[0] + sh2[1] + sh2[2] + sh2[3];
    o1[off] = v1 / sqrtf(t1);
    o2[off] = v2 / sqrtf(t2);
}

// ---------------------------------------------------------------- launch
extern "C" void kernel_launch(void* const* d_in, const int* in_sizes, int n_in,
                              void* d_out, int out_size) {
    const float* f_s  = (const float*)d_in[0];
    const float* f_t  = (const float*)d_in[1];
    const int*   idx  = (const int*)  d_in[2];
    const int*   cidx = (const int*)  d_in[3];
    const float* W_s  = (const float*)d_in[4];
    const float* b_s  = (const float*)d_in[5];
    const float* W_t  = (const float*)d_in[6];
    const float* b_t  = (const float*)d_in[7];
    const float* m1   = (const float*)d_in[8];
    const float* m2   = (const float*)d_in[9];
    float* out = (float*)d_out;
    float* o1 = out + 1;
    float* o2 = out + 1 + MEMELEMS;

    init_kernel<<<1, 1>>>();
    embed_kernel<<<128, 128>>>(f_s, f_t, W_s, b_s, W_t, b_t);
    nce_kernel<<<4096, 256>>>(cidx, m1, m2);
    loss_kernel<<<dim3((KP1 + 255) / 256, BSZ), 256>>>();
    finalize_kernel<<<1, 1>>>(out);
    copy_kernel<<<(MEMELEMS / 4 + 255) / 256, 256>>>((const float4*)m1, (const float4*)m2, o1, o2);
    update_kernel<<<BSZ, 128>>>(idx, m1, m2, o1, o2);
}

// round 2
// speedup vs baseline: 1.0851x; 1.0851x over previous
#include <cuda_runtime.h>
#include <cstdint>

#define BSZ    256
#define FEAT   128
#define KP1    4097
#define PAD    4100            // KP1 padded to mult of 4 for float4 loads
#define NDATA  500000
#define SDIM   1024
#define TDIM   2048
#define MEMELEMS 64000000
#define TOTAL  (BSZ * KP1)     // 1,048,832
#define EPSF   1e-7f
#define MPN    (4096.0f / 500000.0f)

__device__ float g_es[BSZ * FEAT];
__device__ float g_et[BSZ * FEAT];
__device__ float g_out_s[BSZ * PAD];
__device__ float g_out_t[BSZ * PAD];
__device__ float g_sums[3];   // [0]=sum out_t, [1]=sum out_s, [2]=loss sum

// ---------------------------------------------------------------- embeddings (+init fold)
// grid: 128 blocks (64 for es, 64 for et), 128 threads. 4 output rows/block.
__global__ void embed_kernel(const float* __restrict__ f_s, const float* __restrict__ f_t,
                             const float* __restrict__ W_s, const float* __restrict__ b_s,
                             const float* __restrict__ W_t, const float* __restrict__ b_t) {
    if (blockIdx.x == 0 && threadIdx.x == 0) {
        g_sums[0] = 0.f; g_sums[1] = 0.f; g_sums[2] = 0.f;
    }
    __shared__ float fsh[4 * 2048];
    __shared__ float sh[4];
    const bool is_t = blockIdx.x >= 64;
    const int  rb   = (is_t ? blockIdx.x - 64 : blockIdx.x) * 4;
    const float* f    = is_t ? f_t : f_s;
    const float* W    = is_t ? W_t : W_s;
    const float* bias = is_t ? b_t : b_s;
    float*       out  = is_t ? g_et : g_es;
    const int    Kd   = is_t ? TDIM : SDIM;
    const int t = threadIdx.x;

    #pragma unroll
    for (int r = 0; r < 4; ++r)
        for (int k = t; k < Kd; k += 128)
            fsh[r * 2048 + k] = f[(rb + r) * Kd + k];
    __syncthreads();

    float a0 = 0.f, a1 = 0.f, a2 = 0.f, a3 = 0.f;
    for (int k = 0; k < Kd; ++k) {
        float w = W[k * FEAT + t];
        a0 += fsh[k] * w;
        a1 += fsh[2048 + k] * w;
        a2 += fsh[4096 + k] * w;
        a3 += fsh[6144 + k] * w;
    }
    const float bb = bias[t];
    float acc[4] = {a0 + bb, a1 + bb, a2 + bb, a3 + bb};

    const int lane = t & 31, w_ = t >> 5;
    #pragma unroll
    for (int r = 0; r < 4; ++r) {
        float v = acc[r] * acc[r];
        #pragma unroll
        for (int o = 16; o; o >>= 1) v += __shfl_xor_sync(0xffffffffu, v, o);
        if (lane == 0) sh[w_] = v;
        __syncthreads();
        float tot = sh[0] + sh[1] + sh[2] + sh[3];
        __syncthreads();
        out[(rb + r) * FEAT + t] = acc[r] / sqrtf(tot);
    }
}

// ---------------------------------------------------------------- NCE gather + dot + exp
// grid: 4097 blocks x 256 threads = 32776 warps, exactly 32 tasks/warp.
// 4-task software pipeline: 8 independent float4 gathers in flight per warp.
__global__ __launch_bounds__(256) void nce_kernel(const int* __restrict__ cidx,
                                                  const float* __restrict__ m1,
                                                  const float* __restrict__ m2) {
    const int lane = threadIdx.x & 31;
    const int wInB = threadIdx.x >> 5;
    const int wid  = (blockIdx.x * blockDim.x + threadIdx.x) >> 5;
    const int t0   = wid * 32;

    int b = t0 / KP1;
    int k = t0 - b * KP1;
    int bcur = b;
    float4 es4 = *((const float4*)(g_es + b * FEAT) + lane);
    float4 et4 = *((const float4*)(g_et + b * FEAT) + lane);
    float sumT = 0.f, sumS = 0.f;

    #pragma unroll 1
    for (int g = 0; g < 8; ++g) {
        int rows[4], bs[4], ks[4];
        #pragma unroll
        for (int j = 0; j < 4; ++j) {
            rows[j] = __ldg(cidx + t0 + g * 4 + j);
            bs[j] = b; ks[j] = k;
            if (++k == KP1) { k = 0; ++b; }
        }
        float4 A[4], C[4];
        #pragma unroll
        for (int j = 0; j < 4; ++j) {
            A[j] = __ldg((const float4*)m1 + (size_t)rows[j] * 32 + lane);
            C[j] = __ldg((const float4*)m2 + (size_t)rows[j] * 32 + lane);
        }
        float dt[4], ds[4];
        #pragma unroll
        for (int j = 0; j < 4; ++j) {
            if (bs[j] != bcur) {
                bcur = bs[j];
                es4 = *((const float4*)(g_es + bcur * FEAT) + lane);
                et4 = *((const float4*)(g_et + bcur * FEAT) + lane);
            }
            dt[j] = A[j].x * et4.x + A[j].y * et4.y + A[j].z * et4.z + A[j].w * et4.w;
            ds[j] = C[j].x * es4.x + C[j].y * es4.y + C[j].z * es4.z + C[j].w * es4.w;
        }
        #pragma unroll
        for (int o = 16; o; o >>= 1) {
            #pragma unroll
            for (int j = 0; j < 4; ++j) {
                dt[j] += __shfl_xor_sync(0xffffffffu, dt[j], o);
                ds[j] += __shfl_xor_sync(0xffffffffu, ds[j], o);
            }
        }
        if (lane == 0) {
            #pragma unroll
            for (int j = 0; j < 4; ++j) {
                float ot = __expf(dt[j] * (1.0f / 0.07f));
                float os = __expf(ds[j] * (1.0f / 0.07f));
                g_out_t[bs[j] * PAD + ks[j]] = ot;
                g_out_s[bs[j] * PAD + ks[j]] = os;
                sumT += ot; sumS += os;
            }
        }
    }

    __shared__ float shT[8], shS[8];
    if (lane == 0) { shT[wInB] = sumT; shS[wInB] = sumS; }
    __syncthreads();
    if (threadIdx.x == 0) {
        float aT = 0.f, aS = 0.f;
        #pragma unroll
        for (int i = 0; i < 8; ++i) { aT += shT[i]; aS += shS[i]; }
        atomicAdd(&g_sums[0], aT);
        atomicAdd(&g_sums[1], aS);
    }
}

// ---------------------------------------------------------------- loss
// grid: dim3(5, 256), 256 threads; each thread handles 4 consecutive k via float4.
__global__ __launch_bounds__(256) void loss_kernel() {
    const int b = blockIdx.y;
    const int k = (blockIdx.x * 256 + threadIdx.x) * 4;
    const float invZt = (float)TOTAL / ((float)NDATA * g_sums[0]);
    const float invZs = (float)TOTAL / ((float)NDATA * g_sums[1]);
    float acc = 0.f;
    if (k < KP1) {
        float4 vs = *((const float4*)(g_out_s + b * PAD + k));
        float4 vt = *((const float4*)(g_out_t + b * PAD + k));
        float xs[4] = {vs.x, vs.y, vs.z, vs.w};
        float xt[4] = {vt.x, vt.y, vt.z, vt.w};
        #pragma unroll
        for (int c = 0; c < 4; ++c) {
            if (k + c < KP1) {
                float xS = xs[c] * invZs;
                float xT = xt[c] * invZt;
                if (k + c == 0) {
                    acc += logf(xS / (xS + MPN + EPSF)) + logf(xT / (xT + MPN + EPSF));
                } else {
                    // log(mPn/(x+mPn+eps)) == -log(1 + (x+eps)/mPn), numerically safe
                    acc -= logf(1.0f + (xS + EPSF) * (1.0f / MPN));
                    acc -= logf(1.0f + (xT + EPSF) * (1.0f / MPN));
                }
            }
        }
    }
    #pragma unroll
    for (int o = 16; o; o >>= 1) acc += __shfl_xor_sync(0xffffffffu, acc, o);
    __shared__ float sh[8];
    const int lane = threadIdx.x & 31, w_ = threadIdx.x >> 5;
    if (lane == 0) sh[w_] = acc;
    __syncthreads();
    if (threadIdx.x == 0) {
        float tot = 0.f;
        #pragma unroll
        for (int i = 0; i < 8; ++i) tot += sh[i];
        atomicAdd(&g_sums[2], tot);
    }
}

__global__ void finalize_kernel(float* __restrict__ out) {
    out[0] = -g_sums[2] / (float)BSZ;
}

// ---------------------------------------------------------------- memory copy-out
// Vectorized ALIGNED float4 stores to the shifted destination (out+1).
// Chunk i covers o-elements [3+4i, 6+4i]; dst float4 base = out+4 (16B-aligned).
// Each thread does 4 chunks x 2 arrays -> 16 loads in flight.
#define N4 15999999
__global__ __launch_bounds__(256) void copy_kernel(const float* __restrict__ m1,
                                                   const float* __restrict__ m2,
                                                   float* __restrict__ out) {
    const int tid = blockIdx.x * blockDim.x + threadIdx.x;
    const int T = gridDim.x * blockDim.x;   // 4,000,000
    float4* o1b = (float4*)(out + 4);                 // covers o1[3..]
    float4* o2b = (float4*)(out + 4 + MEMELEMS);      // covers o2[3..]
    #pragma unroll
    for (int s = 0; s < 4; ++s) {
        const int i = tid + s * T;
        if (i < N4) {
            float  h1 = __ldg(m1 + 3 + 4 * i);
            float4 v1 = __ldg((const float4*)(m1 + 4 + 4 * i));
            float  h2 = __ldg(m2 + 3 + 4 * i);
            float4 v2 = __ldg((const float4*)(m2 + 4 + 4 * i));
            o1b[i] = make_float4(h1, v1.x, v1.y, v1.z);
            o2b[i] = make_float4(h2, v2.x, v2.y, v2.z);
        }
    }
    if (tid == 0) {
        // heads: o[0..2], tails: o[MEMELEMS-1]
        out[1] = m1[0]; out[2] = m1[1]; out[3] = m1[2];
        out[MEMELEMS] = m1[MEMELEMS - 1];
        out[1 + MEMELEMS] = m2[0]; out[2 + MEMELEMS] = m2[1]; out[3 + MEMELEMS] = m2[2];
        out[2 * MEMELEMS] = m2[MEMELEMS - 1];
    }
}

// ---------------------------------------------------------------- scatter update
__global__ void update_kernel(const int* __restrict__ idx,
                              const float* __restrict__ m1, const float* __restrict__ m2,
                              float* __restrict__ o1, float* __restrict__ o2) {
    const int b = blockIdx.x;
    const int t = threadIdx.x;
    const int row = __ldg(idx + b);
    const size_t off = (size_t)row * FEAT + t;
    float v1 = __ldg(m1 + off) * 0.5f + g_es[b * FEAT + t] * 0.5f;
    float v2 = __ldg(m2 + off) * 0.5f + g_et[b * FEAT + t] * 0.5f;
    float s1 = v1 * v1, s2 = v2 * v2;
    #pragma unroll
    for (int o = 16; o; o >>= 1) {
        s1 += __shfl_xor_sync(0xffffffffu, s1, o);
        s2 += __shfl_xor_sync(0xffffffffu, s2, o);
    }
    __shared__ float sh1[4], sh2[4];
    const int lane = t & 31, w_ = t >> 5;
    if (lane == 0) { sh1[w_] = s1; sh2[w_] = s2; }
    __syncthreads();
    float t1 = sh1[0] + sh1[1] + sh1[2] + sh1[3];
    float t2 = sh2[0] + sh2[1] + sh2[2] + sh2[3];
    o1[off] = v1 / sqrtf(t1);
    o2[off] = v2 / sqrtf(t2);
}

// ---------------------------------------------------------------- launch
extern "C" void kernel_launch(void* const* d_in, const int* in_sizes, int n_in,
                              void* d_out, int out_size) {
    const float* f_s  = (const float*)d_in[0];
    const float* f_t  = (const float*)d_in[1];
    const int*   idx  = (const int*)  d_in[2];
    const int*   cidx = (const int*)  d_in[3];
    const float* W_s  = (const float*)d_in[4];
    const float* b_s  = (const float*)d_in[5];
    const float* W_t  = (const float*)d_in[6];
    const float* b_t  = (const float*)d_in[7];
    const float* m1   = (const float*)d_in[8];
    const float* m2   = (const float*)d_in[9];
    float* out = (float*)d_out;
    float* o1 = out + 1;
    float* o2 = out + 1 + MEMELEMS;

    embed_kernel<<<128, 128>>>(f_s, f_t, W_s, b_s, W_t, b_t);
    nce_kernel<<<4097, 256>>>(cidx, m1, m2);
    loss_kernel<<<dim3(5, 256), 256>>>();
    finalize_kernel<<<1, 1>>>(out);
    copy_kernel<<<15625, 256>>>(m1, m2, out);
    update_kernel<<<BSZ, 128>>>(idx, m1, m2, o1, o2);
}